// round 2
// baseline (speedup 1.0000x reference)
#include <cuda_runtime.h>
#include <math.h>
#include <stdint.h>

#define T_SEQ 200
#define BATCH 4096
#define EMB   100
#define HID   300
#define MID   256

// Scratch (static device allocations are allowed; no cudaMalloc anywhere).
__device__ float g_xw[(size_t)T_SEQ * BATCH * HID]; // [T][B][H] pre-activations (~983MB)
__device__ float g_h[(size_t)BATCH * HID];          // final hidden state

// ---------------------------------------------------------------------------
// Kernel 1: embedding gather + input projection
//   g_xw[t,b,j] = sum_e emb[x[t,b],e] * W_ih[j,e] + b_ih[j] + b_hh[j]
// Tile: 64 flat rows (t*B+b) per CTA. W_ih^T kept in SMEM (pitch 301 ->
// conflict-free STS on transpose-load and conflict-free LDS on compute).
// ---------------------------------------------------------------------------
#define PROJ_TM 64
// floats: WsT 100*301=30100 | e_s 64*100=6400 | bias 300
#define PROJ_WST_F   0
#define PROJ_ES_F    30100
#define PROJ_BIAS_F  (30100 + PROJ_TM*EMB)
#define PROJ_SMEM    ((PROJ_BIAS_F + HID) * 4)

__global__ __launch_bounds__(320, 1)
void proj_kernel(const int* __restrict__ x, const float* __restrict__ emb,
                 const float* __restrict__ W_ih, const float* __restrict__ b_ih,
                 const float* __restrict__ b_hh) {
    extern __shared__ float sm[];
    float* WsT  = sm + PROJ_WST_F;   // [100][301]  WsT[k*301+j] = W_ih[j*100+k]
    float* e_s  = sm + PROJ_ES_F;    // [64][100]
    float* bias = sm + PROJ_BIAS_F;  // [300]
    __shared__ int idx_s[PROJ_TM];

    const int tid = threadIdx.x;
    const long row0 = (long)blockIdx.x * PROJ_TM;

    // Transposed W load: global coalesced, STS stride 301 (conflict-free)
    for (int i = tid; i < HID * EMB; i += 320) {
        int jj = i / EMB, kk = i % EMB;
        WsT[kk * 301 + jj] = W_ih[i];
    }
    if (tid < HID) bias[tid] = b_ih[tid] + b_hh[tid];
    if (tid < PROJ_TM) idx_s[tid] = x[row0 + tid];
    __syncthreads();
    for (int i = tid; i < PROJ_TM * EMB; i += 320) {
        int r = i / EMB, k = i % EMB;
        e_s[r * EMB + k] = emb[(long)idx_s[r] * EMB + k];
    }
    __syncthreads();

    const int j = tid;
    if (j < HID) {
        float acc[PROJ_TM];
        const float bj = bias[j];
        #pragma unroll
        for (int r = 0; r < PROJ_TM; ++r) acc[r] = bj;
        const float4* e4 = (const float4*)e_s;   // row stride 25 float4
        #pragma unroll 1
        for (int k4 = 0; k4 < EMB / 4; ++k4) {
            const float w0 = WsT[(k4 * 4 + 0) * 301 + j];
            const float w1 = WsT[(k4 * 4 + 1) * 301 + j];
            const float w2 = WsT[(k4 * 4 + 2) * 301 + j];
            const float w3 = WsT[(k4 * 4 + 3) * 301 + j];
            #pragma unroll
            for (int r = 0; r < PROJ_TM; ++r) {
                const float4 e = e4[r * 25 + k4];
                float a = acc[r];
                a = fmaf(e.x, w0, a);
                a = fmaf(e.y, w1, a);
                a = fmaf(e.z, w2, a);
                a = fmaf(e.w, w3, a);
                acc[r] = a;
            }
        }
        #pragma unroll
        for (int r = 0; r < PROJ_TM; ++r)
            g_xw[(row0 + r) * HID + j] = acc[r];
    }
}

// ---------------------------------------------------------------------------
// Kernel 2: persistent recurrence. 128 CTAs x 32 batch rows, 200 steps local
// (batch rows are independent -> no cross-CTA sync ever).
//   h_{t+1} = tanh(xw_t + h_t @ W_hh^T)
// W_hh streamed L2->SMEM in 3 chunks of K=100 per step.
// ---------------------------------------------------------------------------
#define REC_TM 32
// floats: hbuf 2*32*300=19200 | Wc 100*301=30100
#define REC_HBUF_F 0
#define REC_WC_F   (2 * REC_TM * HID)
#define REC_SMEM   ((REC_WC_F + 100 * 301) * 4)

__global__ __launch_bounds__(320, 1)
void rec_kernel(const float* __restrict__ W_hh) {
    extern __shared__ float sm[];
    float* hbuf = sm + REC_HBUF_F;   // [2][32][300]
    float* Wc   = sm + REC_WC_F;     // [100][301] chunk, Wc[k*301+j] = W_hh[j*300 + kglob]
    const int tid = threadIdx.x;
    const int b0 = blockIdx.x * REC_TM;
    const int j = tid;

    for (int i = tid; i < 2 * REC_TM * HID; i += 320) hbuf[i] = 0.0f;

    int cur = 0;
    for (int t = 0; t < T_SEQ; ++t) {
        float acc[REC_TM];
        const float* xwrow = g_xw + ((size_t)t * BATCH + b0) * HID;
        if (j < HID) {
            #pragma unroll
            for (int r = 0; r < REC_TM; ++r) acc[r] = xwrow[r * HID + j];
        }
        for (int c = 0; c < 3; ++c) {
            __syncthreads();   // prior compute done reading Wc; h writes visible
            for (int i = tid; i < HID * 100; i += 320) {
                int jj = i / 100, kk = i % 100;
                Wc[kk * 301 + jj] = W_hh[jj * HID + c * 100 + kk];
            }
            __syncthreads();
            if (j < HID) {
                const float4* h4 = (const float4*)(hbuf + cur * REC_TM * HID);
                #pragma unroll 1
                for (int k4 = 0; k4 < 25; ++k4) {
                    const float w0 = Wc[(k4 * 4 + 0) * 301 + j];
                    const float w1 = Wc[(k4 * 4 + 1) * 301 + j];
                    const float w2 = Wc[(k4 * 4 + 2) * 301 + j];
                    const float w3 = Wc[(k4 * 4 + 3) * 301 + j];
                    #pragma unroll
                    for (int r = 0; r < REC_TM; ++r) {
                        const float4 h = h4[r * 75 + c * 25 + k4];
                        float a = acc[r];
                        a = fmaf(h.x, w0, a);
                        a = fmaf(h.y, w1, a);
                        a = fmaf(h.z, w2, a);
                        a = fmaf(h.w, w3, a);
                        acc[r] = a;
                    }
                }
            }
        }
        if (j < HID) {
            if (t == T_SEQ - 1) {
                #pragma unroll
                for (int r = 0; r < REC_TM; ++r)
                    g_h[(size_t)(b0 + r) * HID + j] = tanhf(acc[r]);
            } else {
                float* hn = hbuf + (cur ^ 1) * REC_TM * HID;
                #pragma unroll
                for (int r = 0; r < REC_TM; ++r)
                    hn[r * HID + j] = tanhf(acc[r]);
            }
        }
        cur ^= 1;
        // next iteration's first __syncthreads orders hn writes vs reads
    }
}

// ---------------------------------------------------------------------------
// Kernel 3: head.  hid = relu(h @ W1^T + b1);  out = hid @ W2^T + b2
// 128 CTAs x 32 rows, 256 threads (one per W1 output column).
// ---------------------------------------------------------------------------
// floats: Wc 100*257=25700 | h_s 32*300=9600 | hid 32*257=8224 | W2s 512 | b2s 2
#define HD_WC_F   0
#define HD_HS_F   25700
#define HD_HID_F  (25700 + 32 * HID)
#define HD_W2_F   (HD_HID_F + 32 * 257)
#define HD_B2_F   (HD_W2_F + 2 * MID)
#define HEAD_SMEM ((HD_B2_F + 2) * 4)

__global__ __launch_bounds__(256, 1)
void head_kernel(const float* __restrict__ W1, const float* __restrict__ b1,
                 const float* __restrict__ W2, const float* __restrict__ b2,
                 float* __restrict__ out) {
    extern __shared__ float sm[];
    float* Wc  = sm + HD_WC_F;    // [100][257]
    float* h_s = sm + HD_HS_F;    // [32][300]
    float* hid = sm + HD_HID_F;   // [32][257]
    float* W2s = sm + HD_W2_F;    // [2][256]
    float* b2s = sm + HD_B2_F;    // [2]
    const int tid = threadIdx.x;
    const int b0 = blockIdx.x * 32;

    for (int i = tid; i < 32 * HID; i += 256)
        h_s[i] = g_h[(size_t)b0 * HID + i];
    for (int i = tid; i < 2 * MID; i += 256) W2s[i] = W2[i];
    if (tid < 2) b2s[tid] = b2[tid];

    const int j = tid;  // hidden column, 0..255
    float acc[32];
    const float b1j = b1[j];
    #pragma unroll
    for (int r = 0; r < 32; ++r) acc[r] = b1j;

    for (int c = 0; c < 3; ++c) {
        __syncthreads();
        for (int i = tid; i < MID * 100; i += 256) {
            int jj = i / 100, kk = i % 100;
            Wc[kk * 257 + jj] = W1[jj * HID + c * 100 + kk];
        }
        __syncthreads();
        const float4* h4 = (const float4*)h_s;
        #pragma unroll 1
        for (int k4 = 0; k4 < 25; ++k4) {
            const float w0 = Wc[(k4 * 4 + 0) * 257 + j];
            const float w1 = Wc[(k4 * 4 + 1) * 257 + j];
            const float w2 = Wc[(k4 * 4 + 2) * 257 + j];
            const float w3 = Wc[(k4 * 4 + 3) * 257 + j];
            #pragma unroll
            for (int r = 0; r < 32; ++r) {
                const float4 h = h4[r * 75 + c * 25 + k4];
                float a = acc[r];
                a = fmaf(h.x, w0, a);
                a = fmaf(h.y, w1, a);
                a = fmaf(h.z, w2, a);
                a = fmaf(h.w, w3, a);
                acc[r] = a;
            }
        }
    }
    #pragma unroll
    for (int r = 0; r < 32; ++r) hid[r * 257 + j] = fmaxf(acc[r], 0.0f);
    __syncthreads();

    if (tid < 64) {
        const int r = tid >> 1, cc = tid & 1;
        float s = b2s[cc];
        #pragma unroll 4
        for (int k = 0; k < MID; ++k)
            s = fmaf(hid[r * 257 + k], W2s[cc * MID + k], s);
        out[(b0 + r) * 2 + cc] = s;
    }
}

// ---------------------------------------------------------------------------
extern "C" void kernel_launch(void* const* d_in, const int* in_sizes, int n_in,
                              void* d_out, int out_size) {
    const int*   x    = (const int*)  d_in[0];
    const float* emb  = (const float*)d_in[1];
    const float* W_ih = (const float*)d_in[2];
    const float* b_ih = (const float*)d_in[3];
    const float* W_hh = (const float*)d_in[4];
    const float* b_hh = (const float*)d_in[5];
    const float* W1   = (const float*)d_in[6];
    const float* b1   = (const float*)d_in[7];
    const float* W2   = (const float*)d_in[8];
    const float* b2   = (const float*)d_in[9];
    float* out = (float*)d_out;

    cudaFuncSetAttribute(proj_kernel, cudaFuncAttributeMaxDynamicSharedMemorySize, PROJ_SMEM);
    cudaFuncSetAttribute(rec_kernel,  cudaFuncAttributeMaxDynamicSharedMemorySize, REC_SMEM);
    cudaFuncSetAttribute(head_kernel, cudaFuncAttributeMaxDynamicSharedMemorySize, HEAD_SMEM);

    proj_kernel<<<(T_SEQ * BATCH) / PROJ_TM, 320, PROJ_SMEM>>>(x, emb, W_ih, b_ih, b_hh);
    rec_kernel<<<BATCH / REC_TM, 320, REC_SMEM>>>(W_hh);
    head_kernel<<<BATCH / 32, 256, HEAD_SMEM>>>(W1, b1, W2, b2, out);
}

// round 6
// speedup vs baseline: 2.6123x; 2.6123x over previous
#include <cuda_runtime.h>
#include <cuda_bf16.h>
#include <math.h>
#include <stdint.h>

#define T_SEQ 200
#define BATCH 4096
#define EMB   100
#define HID   300
#define MID   256

#define KC    19      /* K chunks of 16 (K padded 300 -> 304) */
#define NFRG  40      /* total n8 frags (N padded 300 -> 320) */
#define NFW   10      /* n-frags per warp (n-slice of 80) */

// ---------------------------------------------------------------------------
// Static device scratch (no allocation APIs anywhere).
// ---------------------------------------------------------------------------
__device__ __align__(16) float g_xw[(size_t)T_SEQ * BATCH * HID + 8]; // [T][B][H]
__device__ __align__(16) float g_h[(size_t)BATCH * HID];              // final hidden
// Pre-packed B fragments: [kc][nfrag][lane] -> {b0hi, b1hi, b0lo, b1lo}
__device__ __align__(16) uint4 g_Bfrag[KC * NFRG * 32];               // 389120 B

// ---------------------------------------------------------------------------
// Helpers
// ---------------------------------------------------------------------------
__device__ __forceinline__ uint32_t smem_u32(const void* p) {
    uint32_t a;
    asm("{ .reg .u64 t; cvta.to.shared.u64 t, %1; cvt.u32.u64 %0, t; }"
        : "=r"(a) : "l"(p));
    return a;
}

__device__ __forceinline__ void mma_bf16(float d[4], uint32_t a0, uint32_t a1,
                                         uint32_t a2, uint32_t a3,
                                         uint32_t b0, uint32_t b1) {
    asm volatile(
        "mma.sync.aligned.m16n8k16.row.col.f32.bf16.bf16.f32 "
        "{%0,%1,%2,%3}, {%4,%5,%6,%7}, {%8,%9}, {%0,%1,%2,%3};"
        : "+f"(d[0]), "+f"(d[1]), "+f"(d[2]), "+f"(d[3])
        : "r"(a0), "r"(a1), "r"(a2), "r"(a3), "r"(b0), "r"(b1));
}

#define CP_ASYNC16(dst, src) \
    asm volatile("cp.async.cg.shared.global [%0], [%1], 16;" :: "r"(dst), "l"(src) : "memory")
#define CP_COMMIT() asm volatile("cp.async.commit_group;" ::: "memory")
#define CP_WAIT0()  asm volatile("cp.async.wait_group 0;" ::: "memory")

__device__ __forceinline__ float fast_tanh(float v) {
    float e, rc;
    asm("ex2.approx.f32 %0, %1;" : "=f"(e) : "f"(v * 2.885390082f)); // exp(2v)
    asm("rcp.approx.f32 %0, %1;" : "=f"(rc) : "f"(e + 1.0f));
    return fmaf(-2.0f, rc, 1.0f);
}

__device__ __forceinline__ uint32_t pack_bf16(float x, float y) {
    __nv_bfloat16 h0 = __float2bfloat16(x);
    __nv_bfloat16 h1 = __float2bfloat16(y);
    return (uint32_t)__bfloat16_as_ushort(h0) | ((uint32_t)__bfloat16_as_ushort(h1) << 16);
}

// ---------------------------------------------------------------------------
// Kernel 0: pre-pack W_hh into HMMA B fragments (hi/lo split).
// B[k][n] = W_hh[n][k]. Fragment lane mapping (m16n8k16, .row.col):
//   b0 = {B[k=q*2][n], B[q*2+1][n]},  b1 = {B[q*2+8][n], B[q*2+9][n]},
//   n = nfrag*8 + lane/4, q = lane%4, k relative to kc*16.
// ---------------------------------------------------------------------------
__global__ void init_bfrag_kernel(const float* __restrict__ W_hh) {
    int idx = blockIdx.x * 256 + threadIdx.x;
    if (idx >= KC * NFRG * 32) return;
    int kc   = idx / (NFRG * 32);
    int rem  = idx % (NFRG * 32);
    int nf   = rem / 32;
    int lane = rem % 32;
    int n = nf * 8 + (lane >> 2);
    int q = lane & 3;
    float w[4];
    #pragma unroll
    for (int i = 0; i < 4; ++i) {
        int k = kc * 16 + ((i >> 1) ? (q * 2 + 8) : (q * 2)) + (i & 1);
        w[i] = (n < HID && k < HID) ? W_hh[n * HID + k] : 0.0f;
    }
    float hi[4], lo[4];
    #pragma unroll
    for (int i = 0; i < 4; ++i) {
        __nv_bfloat16 h = __float2bfloat16(w[i]);
        hi[i] = __bfloat162float(h);
        lo[i] = w[i] - hi[i];
    }
    uint4 r;
    r.x = pack_bf16(hi[0], hi[1]);
    r.y = pack_bf16(hi[2], hi[3]);
    r.z = pack_bf16(lo[0], lo[1]);
    r.w = pack_bf16(lo[2], lo[3]);
    g_Bfrag[idx] = r;
}

// ---------------------------------------------------------------------------
// Kernel 1: embedding gather + input projection (fp32 SIMT, known-good)
// ---------------------------------------------------------------------------
#define PROJ_TM 64
#define PROJ_WST_F   0
#define PROJ_ES_F    30100
#define PROJ_BIAS_F  (30100 + PROJ_TM * EMB)
#define PROJ_SMEM    ((PROJ_BIAS_F + HID) * 4)

__global__ __launch_bounds__(320, 1)
void proj_kernel(const int* __restrict__ x, const float* __restrict__ emb,
                 const float* __restrict__ W_ih, const float* __restrict__ b_ih,
                 const float* __restrict__ b_hh) {
    extern __shared__ float sm[];
    float* WsT  = sm + PROJ_WST_F;
    float* e_s  = sm + PROJ_ES_F;
    float* bias = sm + PROJ_BIAS_F;
    __shared__ int idx_s[PROJ_TM];
    const int tid = threadIdx.x;
    const long row0 = (long)blockIdx.x * PROJ_TM;

    for (int i = tid; i < HID * EMB; i += 320) {
        int jj = i / EMB, kk = i % EMB;
        WsT[kk * 301 + jj] = W_ih[i];
    }
    if (tid < HID) bias[tid] = b_ih[tid] + b_hh[tid];
    if (tid < PROJ_TM) idx_s[tid] = x[row0 + tid];
    __syncthreads();
    for (int i = tid; i < PROJ_TM * EMB; i += 320) {
        int r = i / EMB, k = i % EMB;
        e_s[r * EMB + k] = emb[(long)idx_s[r] * EMB + k];
    }
    __syncthreads();

    const int j = tid;
    if (j < HID) {
        float acc[PROJ_TM];
        const float bj = bias[j];
        #pragma unroll
        for (int r = 0; r < PROJ_TM; ++r) acc[r] = bj;
        const float4* e4 = (const float4*)e_s;
        #pragma unroll 1
        for (int k4 = 0; k4 < EMB / 4; ++k4) {
            const float w0 = WsT[(k4 * 4 + 0) * 301 + j];
            const float w1 = WsT[(k4 * 4 + 1) * 301 + j];
            const float w2 = WsT[(k4 * 4 + 2) * 301 + j];
            const float w3 = WsT[(k4 * 4 + 3) * 301 + j];
            #pragma unroll
            for (int r = 0; r < PROJ_TM; ++r) {
                const float4 e = e4[r * 25 + k4];
                float a = acc[r];
                a = fmaf(e.x, w0, a); a = fmaf(e.y, w1, a);
                a = fmaf(e.z, w2, a); a = fmaf(e.w, w3, a);
                acc[r] = a;
            }
        }
        #pragma unroll
        for (int r = 0; r < PROJ_TM; ++r)
            g_xw[(row0 + r) * HID + j] = acc[r];
    }
}

// ---------------------------------------------------------------------------
// Kernel 2: HMMA persistent recurrence. 128 CTAs x 32 rows x 200 steps.
//   h_{t+1} = tanh(xw_t + h_t @ W_hh^T), split-bf16 3-term on tensor pipe.
// SMEM: A_hi [32 rows x 328 bf16] @0 (20992B) | A_lo @20992 | XW [32][304 f32] @41984
// ---------------------------------------------------------------------------
#define A_PITCH_B 656           /* 328 bf16 per row */
#define A_LO_OFF  20992
#define XW_OFF    41984
#define XW_PITCH_B 1216         /* 304 floats */
#define REC_SMEM  (XW_OFF + 32 * XW_PITCH_B)   /* 80896 */

__global__ __launch_bounds__(128, 1)
void rec_mma_kernel() {
    extern __shared__ unsigned char smem[];
    const uint32_t sb = smem_u32(smem);
    const int tid  = threadIdx.x;
    const int w    = tid >> 5;
    const int lane = tid & 31;
    const int q    = lane & 3;
    const int mrow = lane >> 2;
    const int b0   = blockIdx.x * 32;

    // zero A images (h0 = 0; padding columns stay 0)
    for (int i = tid * 16; i < XW_OFF; i += 128 * 16)
        *(uint4*)(smem + i) = make_uint4(0, 0, 0, 0);
    __syncthreads();

    const uint4* __restrict__ Bwarp = g_Bfrag + (w * NFW) * 32 + lane;
    const uint32_t abase = (uint32_t)(mrow * A_PITCH_B + q * 4);
    const float* xw_s = (const float*)(smem + XW_OFF);

    float acc[2][NFW][4];
    uint4 Bb[2][NFW];

    #pragma unroll 1
    for (int t = 0; t < T_SEQ; ++t) {
        // stage xw(t) for this CTA's 32 rows: 32 x 300 floats, 16B chunks
        {
            const float* src0 = g_xw + ((size_t)t * BATCH + b0) * HID;
            for (int c = tid; c < 32 * 75; c += 128) {
                int m = c / 75, i = c % 75;
                CP_ASYNC16(sb + XW_OFF + m * XW_PITCH_B + i * 16,
                           src0 + (size_t)m * HID + i * 4);
            }
            CP_COMMIT();
        }

        #pragma unroll
        for (int mf = 0; mf < 2; ++mf)
            #pragma unroll
            for (int f = 0; f < NFW; ++f)
                #pragma unroll
                for (int c = 0; c < 4; ++c) acc[mf][f][c] = 0.0f;

        // prologue: B frags for kc = 0
        #pragma unroll
        for (int f = 0; f < NFW; ++f) Bb[0][f] = Bwarp[(0 * NFRG + f) * 32];

        #pragma unroll
        for (int kc = 0; kc < KC; ++kc) {
            const int cur = kc & 1, nxt = cur ^ 1;
            if (kc + 1 < KC) {
                #pragma unroll
                for (int f = 0; f < NFW; ++f)
                    Bb[nxt][f] = Bwarp[((kc + 1) * NFRG + f) * 32];
            }
            // A fragments for this k-chunk (hi and lo images, 2 m-frags)
            uint32_t ah[2][4], al[2][4];
            #pragma unroll
            for (int mf = 0; mf < 2; ++mf) {
                const uint32_t o = abase + (uint32_t)(mf * 16 * A_PITCH_B + kc * 32);
                ah[mf][0] = *(const uint32_t*)(smem + o);
                ah[mf][1] = *(const uint32_t*)(smem + o + 8 * A_PITCH_B);
                ah[mf][2] = *(const uint32_t*)(smem + o + 16);
                ah[mf][3] = *(const uint32_t*)(smem + o + 8 * A_PITCH_B + 16);
                al[mf][0] = *(const uint32_t*)(smem + A_LO_OFF + o);
                al[mf][1] = *(const uint32_t*)(smem + A_LO_OFF + o + 8 * A_PITCH_B);
                al[mf][2] = *(const uint32_t*)(smem + A_LO_OFF + o + 16);
                al[mf][3] = *(const uint32_t*)(smem + A_LO_OFF + o + 8 * A_PITCH_B + 16);
            }
            #pragma unroll
            for (int f = 0; f < NFW; ++f) {
                const uint4 b = Bb[cur][f];
                #pragma unroll
                for (int mf = 0; mf < 2; ++mf) {
                    mma_bf16(acc[mf][f], ah[mf][0], ah[mf][1], ah[mf][2], ah[mf][3], b.x, b.y);
                    mma_bf16(acc[mf][f], al[mf][0], al[mf][1], al[mf][2], al[mf][3], b.x, b.y);
                    mma_bf16(acc[mf][f], ah[mf][0], ah[mf][1], ah[mf][2], ah[mf][3], b.z, b.w);
                }
            }
        }

        CP_WAIT0();
        __syncthreads();   // all A reads done; xw staged by every thread

        // epilogue: tanh(acc + xw), split, write back A (or g_h at t=199)
        const bool last = (t == T_SEQ - 1);
        #pragma unroll
        for (int mf = 0; mf < 2; ++mf) {
            #pragma unroll
            for (int f = 0; f < NFW; ++f) {
                const int j  = w * 80 + f * 8 + q * 2;
                const int m0 = mf * 16 + mrow;
                const int m1 = m0 + 8;
                float2 x0 = make_float2(0.0f, 0.0f), x1 = make_float2(0.0f, 0.0f);
                if (j < HID) {
                    x0 = *(const float2*)((const char*)xw_s + m0 * XW_PITCH_B + j * 4);
                    x1 = *(const float2*)((const char*)xw_s + m1 * XW_PITCH_B + j * 4);
                }
                const float t00 = fast_tanh(acc[mf][f][0] + x0.x);
                const float t01 = fast_tanh(acc[mf][f][1] + x0.y);
                const float t10 = fast_tanh(acc[mf][f][2] + x1.x);
                const float t11 = fast_tanh(acc[mf][f][3] + x1.y);
                if (last) {
                    if (j < HID) {
                        float* h0p = g_h + (size_t)(b0 + m0) * HID + j;
                        float* h1p = g_h + (size_t)(b0 + m1) * HID + j;
                        h0p[0] = t00; h0p[1] = t01;
                        h1p[0] = t10; h1p[1] = t11;
                    }
                } else {
                    const float h00 = __bfloat162float(__float2bfloat16(t00));
                    const float h01 = __bfloat162float(__float2bfloat16(t01));
                    const float h10 = __bfloat162float(__float2bfloat16(t10));
                    const float h11 = __bfloat162float(__float2bfloat16(t11));
                    const uint32_t o0 = (uint32_t)(m0 * A_PITCH_B + j * 2);
                    const uint32_t o1 = (uint32_t)(m1 * A_PITCH_B + j * 2);
                    *(uint32_t*)(smem + o0) = pack_bf16(h00, h01);
                    *(uint32_t*)(smem + o1) = pack_bf16(h10, h11);
                    *(uint32_t*)(smem + A_LO_OFF + o0) = pack_bf16(t00 - h00, t01 - h01);
                    *(uint32_t*)(smem + A_LO_OFF + o1) = pack_bf16(t10 - h10, t11 - h11);
                }
            }
        }
        __syncthreads();   // A(t+1) fully written before next step reads it
    }
}

// ---------------------------------------------------------------------------
// Kernel 3: head (known-good). hid = relu(h @ W1^T + b1); out = hid @ W2^T + b2
// ---------------------------------------------------------------------------
#define HD_WC_F   0
#define HD_HS_F   25700
#define HD_HID_F  (25700 + 32 * HID)
#define HD_W2_F   (HD_HID_F + 32 * 257)
#define HD_B2_F   (HD_W2_F + 2 * MID)
#define HEAD_SMEM ((HD_B2_F + 2) * 4)

__global__ __launch_bounds__(256, 1)
void head_kernel(const float* __restrict__ W1, const float* __restrict__ b1,
                 const float* __restrict__ W2, const float* __restrict__ b2,
                 float* __restrict__ out) {
    extern __shared__ float sm[];
    float* Wc  = sm + HD_WC_F;
    float* h_s = sm + HD_HS_F;
    float* hid = sm + HD_HID_F;
    float* W2s = sm + HD_W2_F;
    float* b2s = sm + HD_B2_F;
    const int tid = threadIdx.x;
    const int b0 = blockIdx.x * 32;

    for (int i = tid; i < 32 * HID; i += 256)
        h_s[i] = g_h[(size_t)b0 * HID + i];
    for (int i = tid; i < 2 * MID; i += 256) W2s[i] = W2[i];
    if (tid < 2) b2s[tid] = b2[tid];

    const int j = tid;
    float acc[32];
    const float b1j = b1[j];
    #pragma unroll
    for (int r = 0; r < 32; ++r) acc[r] = b1j;

    for (int c = 0; c < 3; ++c) {
        __syncthreads();
        for (int i = tid; i < MID * 100; i += 256) {
            int jj = i / 100, kk = i % 100;
            Wc[kk * 257 + jj] = W1[jj * HID + c * 100 + kk];
        }
        __syncthreads();
        const float4* h4 = (const float4*)h_s;
        #pragma unroll 1
        for (int k4 = 0; k4 < 25; ++k4) {
            const float w0 = Wc[(k4 * 4 + 0) * 257 + j];
            const float w1 = Wc[(k4 * 4 + 1) * 257 + j];
            const float w2 = Wc[(k4 * 4 + 2) * 257 + j];
            const float w3 = Wc[(k4 * 4 + 3) * 257 + j];
            #pragma unroll
            for (int r = 0; r < 32; ++r) {
                const float4 h = h4[r * 75 + c * 25 + k4];
                float a = acc[r];
                a = fmaf(h.x, w0, a); a = fmaf(h.y, w1, a);
                a = fmaf(h.z, w2, a); a = fmaf(h.w, w3, a);
                acc[r] = a;
            }
        }
    }
    #pragma unroll
    for (int r = 0; r < 32; ++r) hid[r * 257 + j] = fmaxf(acc[r], 0.0f);
    __syncthreads();

    if (tid < 64) {
        const int r = tid >> 1, cc = tid & 1;
        float s = b2s[cc];
        #pragma unroll 4
        for (int k = 0; k < MID; ++k)
            s = fmaf(hid[r * 257 + k], W2s[cc * MID + k], s);
        out[(b0 + r) * 2 + cc] = s;
    }
}

// ---------------------------------------------------------------------------
extern "C" void kernel_launch(void* const* d_in, const int* in_sizes, int n_in,
                              void* d_out, int out_size) {
    const int*   x    = (const int*)  d_in[0];
    const float* emb  = (const float*)d_in[1];
    const float* W_ih = (const float*)d_in[2];
    const float* b_ih = (const float*)d_in[3];
    const float* W_hh = (const float*)d_in[4];
    const float* b_hh = (const float*)d_in[5];
    const float* W1   = (const float*)d_in[6];
    const float* b1   = (const float*)d_in[7];
    const float* W2   = (const float*)d_in[8];
    const float* b2   = (const float*)d_in[9];
    float* out = (float*)d_out;

    cudaFuncSetAttribute(proj_kernel,    cudaFuncAttributeMaxDynamicSharedMemorySize, PROJ_SMEM);
    cudaFuncSetAttribute(rec_mma_kernel, cudaFuncAttributeMaxDynamicSharedMemorySize, REC_SMEM);
    cudaFuncSetAttribute(head_kernel,    cudaFuncAttributeMaxDynamicSharedMemorySize, HEAD_SMEM);

    init_bfrag_kernel<<<(KC * NFRG * 32 + 255) / 256, 256>>>(W_hh);
    proj_kernel<<<(T_SEQ * BATCH) / PROJ_TM, 320, PROJ_SMEM>>>(x, emb, W_ih, b_ih, b_hh);
    rec_mma_kernel<<<BATCH / 32, 128, REC_SMEM>>>();
    head_kernel<<<BATCH / 32, 256, HEAD_SMEM>>>(W1, b1, W2, b2, out);
}

// round 8
// speedup vs baseline: 5.8454x; 2.2377x over previous
#include <cuda_runtime.h>
#include <cuda_bf16.h>
#include <math.h>
#include <stdint.h>

#define T_SEQ 200
#define BATCH 4096
#define EMB   100
#define HID   300
#define MID   256
#define VOCAB 50000

#define KC    19      /* K chunks of 16 (K padded 300 -> 304) */
#define NFRG  40      /* total n8 frags (N padded 300 -> 320) */
#define NFW   10      /* n-frags per warp (n-slice of 80) */

#define P_PITCH 304   /* floats per projected-vocab row (16B aligned) */

// ---------------------------------------------------------------------------
// Static device scratch (no allocation APIs anywhere).
// ---------------------------------------------------------------------------
__device__ __align__(16) float g_P[(size_t)VOCAB * P_PITCH];  // projected vocab (61MB)
__device__ __align__(16) float g_h[(size_t)BATCH * HID];      // final hidden
// Pre-packed B fragments: [kc][nfrag][lane] -> {b0hi, b1hi, b0lo, b1lo}
__device__ __align__(16) uint4 g_Bfrag[KC * NFRG * 32];       // 389120 B

// ---------------------------------------------------------------------------
// Helpers
// ---------------------------------------------------------------------------
__device__ __forceinline__ uint32_t smem_u32(const void* p) {
    uint32_t a;
    asm("{ .reg .u64 t; cvta.to.shared.u64 t, %1; cvt.u32.u64 %0, t; }"
        : "=r"(a) : "l"(p));
    return a;
}

__device__ __forceinline__ void mma_bf16(float d[4], uint32_t a0, uint32_t a1,
                                         uint32_t a2, uint32_t a3,
                                         uint32_t b0, uint32_t b1) {
    asm volatile(
        "mma.sync.aligned.m16n8k16.row.col.f32.bf16.bf16.f32 "
        "{%0,%1,%2,%3}, {%4,%5,%6,%7}, {%8,%9}, {%0,%1,%2,%3};"
        : "+f"(d[0]), "+f"(d[1]), "+f"(d[2]), "+f"(d[3])
        : "r"(a0), "r"(a1), "r"(a2), "r"(a3), "r"(b0), "r"(b1));
}

#define CP_ASYNC16(dst, src) \
    asm volatile("cp.async.cg.shared.global [%0], [%1], 16;" :: "r"(dst), "l"(src) : "memory")
#define CP_COMMIT() asm volatile("cp.async.commit_group;" ::: "memory")
#define CP_WAIT0()  asm volatile("cp.async.wait_group 0;" ::: "memory")

__device__ __forceinline__ float fast_tanh(float v) {
    float e, rc;
    asm("ex2.approx.f32 %0, %1;" : "=f"(e) : "f"(v * 2.885390082f)); // exp(2v)
    asm("rcp.approx.f32 %0, %1;" : "=f"(rc) : "f"(e + 1.0f));
    return fmaf(-2.0f, rc, 1.0f);
}

__device__ __forceinline__ uint32_t pack_bf16(float x, float y) {
    __nv_bfloat16 h0 = __float2bfloat16(x);
    __nv_bfloat16 h1 = __float2bfloat16(y);
    return (uint32_t)__bfloat16_as_ushort(h0) | ((uint32_t)__bfloat16_as_ushort(h1) << 16);
}

// ---------------------------------------------------------------------------
// Kernel 0: pre-pack W_hh into HMMA B fragments (hi/lo split). (unchanged)
// ---------------------------------------------------------------------------
__global__ void init_bfrag_kernel(const float* __restrict__ W_hh) {
    int idx = blockIdx.x * 256 + threadIdx.x;
    if (idx >= KC * NFRG * 32) return;
    int kc   = idx / (NFRG * 32);
    int rem  = idx % (NFRG * 32);
    int nf   = rem / 32;
    int lane = rem % 32;
    int n = nf * 8 + (lane >> 2);
    int q = lane & 3;
    float w[4];
    #pragma unroll
    for (int i = 0; i < 4; ++i) {
        int k = kc * 16 + ((i >> 1) ? (q * 2 + 8) : (q * 2)) + (i & 1);
        w[i] = (n < HID && k < HID) ? W_hh[n * HID + k] : 0.0f;
    }
    float hi[4], lo[4];
    #pragma unroll
    for (int i = 0; i < 4; ++i) {
        __nv_bfloat16 h = __float2bfloat16(w[i]);
        hi[i] = __bfloat162float(h);
        lo[i] = w[i] - hi[i];
    }
    uint4 r;
    r.x = pack_bf16(hi[0], hi[1]);
    r.y = pack_bf16(hi[2], hi[3]);
    r.z = pack_bf16(lo[0], lo[1]);
    r.w = pack_bf16(lo[2], lo[3]);
    g_Bfrag[idx] = r;
}

// ---------------------------------------------------------------------------
// Kernel 1: vocab projection.  g_P[v][j] = emb[v]@W_ih[j] + b_ih[j] + b_hh[j]
// Only 50000 rows (16x less work than per-token). 64 vocab rows per CTA.
// ---------------------------------------------------------------------------
#define VP_TM 64
#define VP_WST_F   0
#define VP_ES_F    30100
#define VP_BIAS_F  (30100 + VP_TM * EMB)
#define VP_SMEM    ((VP_BIAS_F + HID) * 4)

__global__ __launch_bounds__(320, 1)
void vocab_proj_kernel(const float* __restrict__ emb,
                       const float* __restrict__ W_ih, const float* __restrict__ b_ih,
                       const float* __restrict__ b_hh) {
    extern __shared__ float sm[];
    float* WsT  = sm + VP_WST_F;    // [100][301]
    float* e_s  = sm + VP_ES_F;     // [64][100]
    float* bias = sm + VP_BIAS_F;   // [300]
    const int tid = threadIdx.x;
    const long v0 = (long)blockIdx.x * VP_TM;

    for (int i = tid; i < HID * EMB; i += 320) {
        int jj = i / EMB, kk = i % EMB;
        WsT[kk * 301 + jj] = W_ih[i];
    }
    if (tid < HID) bias[tid] = b_ih[tid] + b_hh[tid];
    __syncthreads();
    for (int i = tid; i < VP_TM * EMB; i += 320) {
        int r = i / EMB, k = i % EMB;
        long v = v0 + r;
        e_s[r * EMB + k] = (v < VOCAB) ? emb[v * EMB + k] : 0.0f;
    }
    __syncthreads();

    const int j = tid;
    if (j < HID) {
        float acc[VP_TM];
        const float bj = bias[j];
        #pragma unroll
        for (int r = 0; r < VP_TM; ++r) acc[r] = bj;
        const float4* e4 = (const float4*)e_s;
        #pragma unroll 1
        for (int k4 = 0; k4 < EMB / 4; ++k4) {
            const float w0 = WsT[(k4 * 4 + 0) * 301 + j];
            const float w1 = WsT[(k4 * 4 + 1) * 301 + j];
            const float w2 = WsT[(k4 * 4 + 2) * 301 + j];
            const float w3 = WsT[(k4 * 4 + 3) * 301 + j];
            #pragma unroll
            for (int r = 0; r < VP_TM; ++r) {
                const float4 e = e4[r * 25 + k4];
                float a = acc[r];
                a = fmaf(e.x, w0, a); a = fmaf(e.y, w1, a);
                a = fmaf(e.z, w2, a); a = fmaf(e.w, w3, a);
                acc[r] = a;
            }
        }
        #pragma unroll
        for (int r = 0; r < VP_TM; ++r)
            if (v0 + r < VOCAB)
                g_P[(size_t)(v0 + r) * P_PITCH + j] = acc[r];
    }
}

// ---------------------------------------------------------------------------
// Kernel 2: HMMA persistent recurrence with fused xw gather.
// 128 CTAs x 32 rows x 200 steps; xw rows gathered from g_P[x[t,b]] (L2-hot).
// SMEM: A_hi @0 (20992) | A_lo @20992 | XW [32][304 f32] @41984 (38912)
//       | idx [200][32] @80896 (25600)  -> total 106496
// ---------------------------------------------------------------------------
#define A_PITCH_B 656           /* 328 bf16 per row */
#define A_LO_OFF  20992
#define XW_OFF    41984
#define XW_PITCH_B 1216         /* 304 floats */
#define IDX_OFF   (XW_OFF + 32 * XW_PITCH_B)   /* 80896 */
#define REC_SMEM  (IDX_OFF + T_SEQ * 32 * 4)   /* 106496 */

__global__ __launch_bounds__(128, 1)
void rec_mma_kernel(const int* __restrict__ x) {
    extern __shared__ unsigned char smem[];
    const uint32_t sb = smem_u32(smem);
    const int tid  = threadIdx.x;
    const int w    = tid >> 5;
    const int lane = tid & 31;
    const int q    = lane & 3;
    const int mrow = lane >> 2;
    const int b0   = blockIdx.x * 32;

    // zero A images (h0 = 0; padding columns stay 0)
    for (int i = tid * 16; i < XW_OFF; i += 128 * 16)
        *(uint4*)(smem + i) = make_uint4(0, 0, 0, 0);

    // stage ALL indices for this CTA's 32 batch rows: idx[t][r] = x[t*BATCH+b0+r]
    int* idx_s = (int*)(smem + IDX_OFF);
    for (int i = tid; i < T_SEQ * 32; i += 128) {
        int t = i >> 5, r = i & 31;
        idx_s[i] = x[(size_t)t * BATCH + b0 + r];
    }
    __syncthreads();

    const uint4* __restrict__ Bwarp = g_Bfrag + (w * NFW) * 32 + lane;
    const uint32_t abase = (uint32_t)(mrow * A_PITCH_B + q * 4);
    const float* xw_s = (const float*)(smem + XW_OFF);

    float acc[2][NFW][4];
    uint4 Bb[2][NFW];

    #pragma unroll 1
    for (int t = 0; t < T_SEQ; ++t) {
        // gather xw(t): 32 rows x 300 floats from g_P[idx], 16B chunks (L2-hot)
        {
            const int* idx_t = idx_s + t * 32;
            for (int c = tid; c < 32 * 75; c += 128) {
                int m = c / 75, i = c % 75;
                const float* src = g_P + (size_t)idx_t[m] * P_PITCH + i * 4;
                CP_ASYNC16(sb + XW_OFF + m * XW_PITCH_B + i * 16, src);
            }
            CP_COMMIT();
        }

        #pragma unroll
        for (int mf = 0; mf < 2; ++mf)
            #pragma unroll
            for (int f = 0; f < NFW; ++f)
                #pragma unroll
                for (int c = 0; c < 4; ++c) acc[mf][f][c] = 0.0f;

        // prologue: B frags for kc = 0
        #pragma unroll
        for (int f = 0; f < NFW; ++f) Bb[0][f] = Bwarp[(0 * NFRG + f) * 32];

        #pragma unroll
        for (int kc = 0; kc < KC; ++kc) {
            const int cur = kc & 1, nxt = cur ^ 1;
            if (kc + 1 < KC) {
                #pragma unroll
                for (int f = 0; f < NFW; ++f)
                    Bb[nxt][f] = Bwarp[((kc + 1) * NFRG + f) * 32];
            }
            uint32_t ah[2][4], al[2][4];
            #pragma unroll
            for (int mf = 0; mf < 2; ++mf) {
                const uint32_t o = abase + (uint32_t)(mf * 16 * A_PITCH_B + kc * 32);
                ah[mf][0] = *(const uint32_t*)(smem + o);
                ah[mf][1] = *(const uint32_t*)(smem + o + 8 * A_PITCH_B);
                ah[mf][2] = *(const uint32_t*)(smem + o + 16);
                ah[mf][3] = *(const uint32_t*)(smem + o + 8 * A_PITCH_B + 16);
                al[mf][0] = *(const uint32_t*)(smem + A_LO_OFF + o);
                al[mf][1] = *(const uint32_t*)(smem + A_LO_OFF + o + 8 * A_PITCH_B);
                al[mf][2] = *(const uint32_t*)(smem + A_LO_OFF + o + 16);
                al[mf][3] = *(const uint32_t*)(smem + A_LO_OFF + o + 8 * A_PITCH_B + 16);
            }
            #pragma unroll
            for (int f = 0; f < NFW; ++f) {
                const uint4 b = Bb[cur][f];
                #pragma unroll
                for (int mf = 0; mf < 2; ++mf) {
                    mma_bf16(acc[mf][f], ah[mf][0], ah[mf][1], ah[mf][2], ah[mf][3], b.x, b.y);
                    mma_bf16(acc[mf][f], al[mf][0], al[mf][1], al[mf][2], al[mf][3], b.x, b.y);
                    mma_bf16(acc[mf][f], ah[mf][0], ah[mf][1], ah[mf][2], ah[mf][3], b.z, b.w);
                }
            }
        }

        CP_WAIT0();
        __syncthreads();   // all A reads done; xw staged

        // epilogue: tanh(acc + xw), split, write back A (or g_h at t=199)
        const bool last = (t == T_SEQ - 1);
        #pragma unroll
        for (int mf = 0; mf < 2; ++mf) {
            #pragma unroll
            for (int f = 0; f < NFW; ++f) {
                const int j  = w * 80 + f * 8 + q * 2;
                const int m0 = mf * 16 + mrow;
                const int m1 = m0 + 8;
                float2 x0 = make_float2(0.0f, 0.0f), x1 = make_float2(0.0f, 0.0f);
                if (j < HID) {
                    x0 = *(const float2*)((const char*)xw_s + m0 * XW_PITCH_B + j * 4);
                    x1 = *(const float2*)((const char*)xw_s + m1 * XW_PITCH_B + j * 4);
                }
                const float t00 = fast_tanh(acc[mf][f][0] + x0.x);
                const float t01 = fast_tanh(acc[mf][f][1] + x0.y);
                const float t10 = fast_tanh(acc[mf][f][2] + x1.x);
                const float t11 = fast_tanh(acc[mf][f][3] + x1.y);
                if (last) {
                    if (j < HID) {
                        float* h0p = g_h + (size_t)(b0 + m0) * HID + j;
                        float* h1p = g_h + (size_t)(b0 + m1) * HID + j;
                        h0p[0] = t00; h0p[1] = t01;
                        h1p[0] = t10; h1p[1] = t11;
                    }
                } else {
                    const float h00 = __bfloat162float(__float2bfloat16(t00));
                    const float h01 = __bfloat162float(__float2bfloat16(t01));
                    const float h10 = __bfloat162float(__float2bfloat16(t10));
                    const float h11 = __bfloat162float(__float2bfloat16(t11));
                    const uint32_t o0 = (uint32_t)(m0 * A_PITCH_B + j * 2);
                    const uint32_t o1 = (uint32_t)(m1 * A_PITCH_B + j * 2);
                    *(uint32_t*)(smem + o0) = pack_bf16(h00, h01);
                    *(uint32_t*)(smem + o1) = pack_bf16(h10, h11);
                    *(uint32_t*)(smem + A_LO_OFF + o0) = pack_bf16(t00 - h00, t01 - h01);
                    *(uint32_t*)(smem + A_LO_OFF + o1) = pack_bf16(t10 - h10, t11 - h11);
                }
            }
        }
        __syncthreads();   // A(t+1) fully written before next step reads it
    }
}

// ---------------------------------------------------------------------------
// Kernel 3: head (known-good). hid = relu(h @ W1^T + b1); out = hid @ W2^T + b2
// ---------------------------------------------------------------------------
#define HD_WC_F   0
#define HD_HS_F   25700
#define HD_HID_F  (25700 + 32 * HID)
#define HD_W2_F   (HD_HID_F + 32 * 257)
#define HD_B2_F   (HD_W2_F + 2 * MID)
#define HEAD_SMEM ((HD_B2_F + 2) * 4)

__global__ __launch_bounds__(256, 1)
void head_kernel(const float* __restrict__ W1, const float* __restrict__ b1,
                 const float* __restrict__ W2, const float* __restrict__ b2,
                 float* __restrict__ out) {
    extern __shared__ float sm[];
    float* Wc  = sm + HD_WC_F;
    float* h_s = sm + HD_HS_F;
    float* hid = sm + HD_HID_F;
    float* W2s = sm + HD_W2_F;
    float* b2s = sm + HD_B2_F;
    const int tid = threadIdx.x;
    const int b0 = blockIdx.x * 32;

    for (int i = tid; i < 32 * HID; i += 256)
        h_s[i] = g_h[(size_t)b0 * HID + i];
    for (int i = tid; i < 2 * MID; i += 256) W2s[i] = W2[i];
    if (tid < 2) b2s[tid] = b2[tid];

    const int j = tid;
    float acc[32];
    const float b1j = b1[j];
    #pragma unroll
    for (int r = 0; r < 32; ++r) acc[r] = b1j;

    for (int c = 0; c < 3; ++c) {
        __syncthreads();
        for (int i = tid; i < MID * 100; i += 256) {
            int jj = i / 100, kk = i % 100;
            Wc[kk * 257 + jj] = W1[jj * HID + c * 100 + kk];
        }
        __syncthreads();
        const float4* h4 = (const float4*)h_s;
        #pragma unroll 1
        for (int k4 = 0; k4 < 25; ++k4) {
            const float w0 = Wc[(k4 * 4 + 0) * 257 + j];
            const float w1 = Wc[(k4 * 4 + 1) * 257 + j];
            const float w2 = Wc[(k4 * 4 + 2) * 257 + j];
            const float w3 = Wc[(k4 * 4 + 3) * 257 + j];
            #pragma unroll
            for (int r = 0; r < 32; ++r) {
                const float4 h = h4[r * 75 + c * 25 + k4];
                float a = acc[r];
                a = fmaf(h.x, w0, a); a = fmaf(h.y, w1, a);
                a = fmaf(h.z, w2, a); a = fmaf(h.w, w3, a);
                acc[r] = a;
            }
        }
    }
    #pragma unroll
    for (int r = 0; r < 32; ++r) hid[r * 257 + j] = fmaxf(acc[r], 0.0f);
    __syncthreads();

    if (tid < 64) {
        const int r = tid >> 1, cc = tid & 1;
        float s = b2s[cc];
        #pragma unroll 4
        for (int k = 0; k < MID; ++k)
            s = fmaf(hid[r * 257 + k], W2s[cc * MID + k], s);
        out[(b0 + r) * 2 + cc] = s;
    }
}

// ---------------------------------------------------------------------------
extern "C" void kernel_launch(void* const* d_in, const int* in_sizes, int n_in,
                              void* d_out, int out_size) {
    const int*   x    = (const int*)  d_in[0];
    const float* emb  = (const float*)d_in[1];
    const float* W_ih = (const float*)d_in[2];
    const float* b_ih = (const float*)d_in[3];
    const float* W_hh = (const float*)d_in[4];
    const float* b_hh = (const float*)d_in[5];
    const float* W1   = (const float*)d_in[6];
    const float* b1   = (const float*)d_in[7];
    const float* W2   = (const float*)d_in[8];
    const float* b2   = (const float*)d_in[9];
    float* out = (float*)d_out;

    cudaFuncSetAttribute(vocab_proj_kernel, cudaFuncAttributeMaxDynamicSharedMemorySize, VP_SMEM);
    cudaFuncSetAttribute(rec_mma_kernel,    cudaFuncAttributeMaxDynamicSharedMemorySize, REC_SMEM);
    cudaFuncSetAttribute(head_kernel,       cudaFuncAttributeMaxDynamicSharedMemorySize, HEAD_SMEM);

    init_bfrag_kernel<<<(KC * NFRG * 32 + 255) / 256, 256>>>(W_hh);
    vocab_proj_kernel<<<(VOCAB + VP_TM - 1) / VP_TM, 320, VP_SMEM>>>(emb, W_ih, b_ih, b_hh);
    rec_mma_kernel<<<BATCH / 32, 128, REC_SMEM>>>(x);
    head_kernel<<<BATCH / 32, 256, HEAD_SMEM>>>(W1, b1, W2, b2, out);
}